// round 15
// baseline (speedup 1.0000x reference)
#include <cuda_runtime.h>
#include <cuda_fp16.h>
#include <cstdint>

// Sparse MoE FFN: T=8192 tokens, H=1024, E=8 experts, top-2 routing.
// fp16 mma m16n8k16 (fp32 accum), BK=32, 4-stage cp.async, reg-double-buffered
// ldmatrix fragments, persistent work-stealing tile scheduler (296 CTAs).

#define NTOK 8192
#define HDIM 1024
#define NEXP 8

#define BM 128
#define BN 128
#define BK 32                   // halves per k-chunk
#define NC (HDIM / BK)          // 32 chunks
#define STAGES 4
#define ROWH 40                 // padded row stride in halves (80 B) -> conflict-free
#define TILEH (BM * ROWH)
#define STAGEH (2 * TILEH)
#define SMEM_BYTES (STAGES * STAGEH * 2)   // 81920 B
#define NCTA 296                // 148 SMs x 2 CTAs

// Routing + half scratch. g_cnt[0..7] = expert counts, g_cnt[8] = work counter.
__device__ int    g_cnt[16];
__device__ int    g_tok[NEXP][NTOK];
__device__ float  g_gw [NEXP][NTOK];
__device__ float  g_beT[NEXP * HDIM];    // bias transposed: [e][h]
__device__ __half g_xh [NTOK * HDIM];
__device__ __half g_weh[NTOK * HDIM];

__device__ __forceinline__ uint32_t pack_h2(float lo, float hi) {
    uint32_t r;
    asm("cvt.rn.f16x2.f32 %0, %1, %2;" : "=r"(r) : "f"(hi), "f"(lo));
    return r;
}

// Fused: blocks [0,1024) gate + convert x + zero out row;
//        blocks [1024,1536) convert We (+ bias transpose in block 1024).
__global__ __launch_bounds__(256) void gate_conv_kernel(
        const float* __restrict__ x,
        const float* __restrict__ Wg,
        const float* __restrict__ bg,
        const float* __restrict__ We,
        const float* __restrict__ be,
        float* __restrict__ out)
{
    if (blockIdx.x >= NTOK / 8) {
        const int bid = blockIdx.x - NTOK / 8;
        if (bid == 0) {
            for (int i = threadIdx.x; i < NEXP * HDIM; i += 256) {
                const int e = i >> 10;
                const int h = i & (HDIM - 1);
                g_beT[i] = be[h * NEXP + e];
            }
        }
        const float4* src = reinterpret_cast<const float4*>(We);
        uint2* dst = reinterpret_cast<uint2*>(g_weh);
        const int n = NTOK * HDIM / 4;
        const int stride = 512 * 256;
        for (int i = bid * 256 + threadIdx.x; i < n; i += stride) {
            const float4 v = src[i];
            uint2 o;
            o.x = pack_h2(v.x, v.y);
            o.y = pack_h2(v.z, v.w);
            dst[i] = o;
        }
        return;
    }

    const int warp = threadIdx.x >> 5;
    const int lane = threadIdx.x & 31;
    const int t = blockIdx.x * 8 + warp;

    const float4* x4 = reinterpret_cast<const float4*>(x) + (size_t)t * (HDIM / 4);
    const float4* w4 = reinterpret_cast<const float4*>(Wg);
    uint2* xo = reinterpret_cast<uint2*>(g_xh) + (size_t)t * (HDIM / 4);
    float4* orow = reinterpret_cast<float4*>(out) + (size_t)t * (HDIM / 4);
    const float4 zero4 = make_float4(0.f, 0.f, 0.f, 0.f);

    float acc[NEXP];
#pragma unroll
    for (int e = 0; e < NEXP; ++e) acc[e] = 0.f;

#pragma unroll
    for (int j = 0; j < 8; ++j) {
        const int i4 = lane + j * 32;
        const float4 xv = x4[i4];
        orow[i4] = zero4;                 // zero the output row (replaces memset)
        uint2 o;
        o.x = pack_h2(xv.x, xv.y);
        o.y = pack_h2(xv.z, xv.w);
        xo[i4] = o;
#pragma unroll
        for (int e = 0; e < NEXP; ++e) {
            const float4 wv = w4[e * (HDIM / 4) + i4];
            acc[e] = fmaf(xv.x, wv.x, acc[e]);
            acc[e] = fmaf(xv.y, wv.y, acc[e]);
            acc[e] = fmaf(xv.z, wv.z, acc[e]);
            acc[e] = fmaf(xv.w, wv.w, acc[e]);
        }
    }
#pragma unroll
    for (int e = 0; e < NEXP; ++e) {
#pragma unroll
        for (int off = 16; off > 0; off >>= 1)
            acc[e] += __shfl_xor_sync(0xffffffffu, acc[e], off);
    }

    if (lane == 0) {
        float l[NEXP];
#pragma unroll
        for (int e = 0; e < NEXP; ++e) l[e] = acc[e] + bg[e];
        int e0 = 0;
#pragma unroll
        for (int e = 1; e < NEXP; ++e) if (l[e] > l[e0]) e0 = e;
        int e1 = (e0 == 0) ? 1 : 0;
#pragma unroll
        for (int e = 0; e < NEXP; ++e) {
            if (e == e0) continue;
            if (l[e] > l[e1]) e1 = e;
        }
        const float d = expf(l[e1] - l[e0]);
        const float s = 1.f / (1.f + d);
        int p0 = atomicAdd(&g_cnt[e0], 1);
        g_tok[e0][p0] = t; g_gw[e0][p0] = s;
        int p1 = atomicAdd(&g_cnt[e1], 1);
        g_tok[e1][p1] = t; g_gw[e1][p1] = d * s;
    }
}

__device__ __forceinline__ void cpasync16(void* dst, const void* src) {
    unsigned d = (unsigned)__cvta_generic_to_shared(dst);
    asm volatile("cp.async.cg.shared.global [%0], [%1], 16;" :: "r"(d), "l"(src));
}
__device__ __forceinline__ void ldsm_x4(uint32_t* r, uint32_t addr) {
    asm volatile("ldmatrix.sync.aligned.m8n8.x4.shared.b16 {%0,%1,%2,%3}, [%4];"
                 : "=r"(r[0]), "=r"(r[1]), "=r"(r[2]), "=r"(r[3]) : "r"(addr));
}
__device__ __forceinline__ void mma_f16(float* c, const uint32_t* a, const uint32_t* b) {
    asm volatile(
        "mma.sync.aligned.m16n8k16.row.col.f32.f16.f16.f32 "
        "{%0,%1,%2,%3}, {%4,%5,%6,%7}, {%8,%9}, {%0,%1,%2,%3};"
        : "+f"(c[0]), "+f"(c[1]), "+f"(c[2]), "+f"(c[3])
        : "r"(a[0]), "r"(a[1]), "r"(a[2]), "r"(a[3]), "r"(b[0]), "r"(b[1]));
}

// Persistent grouped GEMM: 296 CTAs pop (expert, m-tile, h-tile) work items.
__global__ __launch_bounds__(256, 2) void moe_gemm_f16(
        float* __restrict__ out)
{
    extern __shared__ __half smem[];
    __shared__ int s_idx;
    const uint32_t sbase = (uint32_t)__cvta_generic_to_shared(smem);

    const int tid  = threadIdx.x;
    const int wid  = tid >> 5;
    const int lane = tid & 31;
    const int wm   = (wid & 1) * 64;
    const int wn   = (wid >> 1) * 32;
    const int g    = lane >> 2;
    const int t4   = lane & 3;

    const int lrow = tid >> 2;          // 0..63
    const int lch  = (tid & 3) * 8;     // half offset within row: 0,8,16,24

    // ldmatrix lane-address bases (bytes, within a stage).
    const uint32_t a_lane = (uint32_t)(((wm + (lane & 15)) * ROWH + (lane >> 4) * 8) * 2);
    const uint32_t b_lane = (uint32_t)(((wn + ((lane >> 4) << 3) + (lane & 7)) * ROWH
                                        + ((lane >> 3) & 1) * 8) * 2 + TILEH * 2);

    // Total tile count across experts.
    int total = 0;
#pragma unroll
    for (int e = 0; e < NEXP; ++e)
        total += ((g_cnt[e] + BM - 1) >> 7) << 3;

    for (;;) {
        if (tid == 0) s_idx = atomicAdd(&g_cnt[8], 1);
        __syncthreads();
        const int idx = s_idx;
        if (idx >= total) break;

        // Decode idx -> (e, m0, h0); m-major, h inner (consecutive idx share A).
        int e = 0, rem = idx, cnt;
        for (;;) {
            cnt = g_cnt[e];
            const int te = ((cnt + BM - 1) >> 7) << 3;
            if (rem < te) break;
            rem -= te;
            ++e;
        }
        const int m0 = (rem >> 3) * BM;
        const int h0 = (rem & 7) * BN;

        // Per-tile load sources.
        const int r0 = min(m0 + lrow,      cnt - 1);
        const int r1 = min(m0 + lrow + 64, cnt - 1);
        const __half* aptr0 = g_xh + (size_t)g_tok[e][r0] * HDIM + lch;
        const __half* aptr1 = g_xh + (size_t)g_tok[e][r1] * HDIM + lch;
        const __half* bptr0 = g_weh + ((size_t)(h0 + lrow)      * NEXP + e) * HDIM + lch;
        const __half* bptr1 = g_weh + ((size_t)(h0 + lrow + 64) * NEXP + e) * HDIM + lch;
        const int sd0 = lrow * ROWH + lch;
        const int sd1 = (lrow + 64) * ROWH + lch;

        float c[4][4][4];
#pragma unroll
        for (int i = 0; i < 4; ++i)
#pragma unroll
            for (int j = 0; j < 4; ++j)
#pragma unroll
                for (int q = 0; q < 4; ++q) c[i][j][q] = 0.f;

        uint32_t af[2][4][4], bf[2][2][4];

        // Prologue: commit chunks 0..2 into stages 0..2.
#pragma unroll
        for (int cpre = 0; cpre < STAGES - 1; ++cpre) {
            __half* sA = smem + cpre * STAGEH;
            __half* sB = sA + TILEH;
            const int k = cpre * BK;
            cpasync16(&sA[sd0], aptr0 + k);
            cpasync16(&sA[sd1], aptr1 + k);
            cpasync16(&sB[sd0], bptr0 + k);
            cpasync16(&sB[sd1], bptr1 + k);
            asm volatile("cp.async.commit_group;");
        }
        asm volatile("cp.async.wait_group 2;" ::: "memory");
        __syncthreads();

        // Frags (chunk 0, ks 0) -> buffer 0.
#pragma unroll
        for (int mc = 0; mc < 4; ++mc)
            ldsm_x4(af[0][mc], sbase + a_lane + (uint32_t)(mc * 16 * ROWH * 2));
#pragma unroll
        for (int p = 0; p < 2; ++p)
            ldsm_x4(bf[0][p], sbase + b_lane + (uint32_t)(p * 16 * ROWH * 2));

        for (int ck = 0; ck < NC; ++ck) {
            if (ck + 3 < NC) {
                const int ns = (ck + 3) % STAGES;
                const int k  = (ck + 3) * BK;
                __half* sA = smem + ns * STAGEH;
                __half* sB = sA + TILEH;
                cpasync16(&sA[sd0], aptr0 + k);
                cpasync16(&sA[sd1], aptr1 + k);
                cpasync16(&sB[sd0], bptr0 + k);
                cpasync16(&sB[sd1], bptr1 + k);
                asm volatile("cp.async.commit_group;");
            }

            const uint32_t stg = sbase + (uint32_t)((ck % STAGES) * STAGEH * 2);
#pragma unroll
            for (int ks = 0; ks < 2; ++ks) {
                const int cur = ks & 1;
                const int nxt = cur ^ 1;
                if (ks == 0) {
#pragma unroll
                    for (int mc = 0; mc < 4; ++mc)
                        ldsm_x4(af[nxt][mc],
                                stg + a_lane + (uint32_t)(mc * 16 * ROWH * 2) + 32u);
#pragma unroll
                    for (int p = 0; p < 2; ++p)
                        ldsm_x4(bf[nxt][p],
                                stg + b_lane + (uint32_t)(p * 16 * ROWH * 2) + 32u);
                } else if (ck + 1 < NC) {
                    if (ck + 3 < NC) {
                        asm volatile("cp.async.wait_group 2;" ::: "memory");
                    } else if (ck + 2 < NC) {
                        asm volatile("cp.async.wait_group 1;" ::: "memory");
                    } else {
                        asm volatile("cp.async.wait_group 0;" ::: "memory");
                    }
                    __syncthreads();
                    const uint32_t nstg =
                        sbase + (uint32_t)(((ck + 1) % STAGES) * STAGEH * 2);
#pragma unroll
                    for (int mc = 0; mc < 4; ++mc)
                        ldsm_x4(af[nxt][mc],
                                nstg + a_lane + (uint32_t)(mc * 16 * ROWH * 2));
#pragma unroll
                    for (int p = 0; p < 2; ++p)
                        ldsm_x4(bf[nxt][p],
                                nstg + b_lane + (uint32_t)(p * 16 * ROWH * 2));
                }
#pragma unroll
                for (int mc = 0; mc < 4; ++mc)
#pragma unroll
                    for (int nc = 0; nc < 4; ++nc)
                        mma_f16(c[mc][nc], af[cur][mc], &bf[cur][nc >> 1][(nc & 1) * 2]);
            }
        }

        // Epilogue: out[tok,h] += w * (c + beT[e][h]).
        const float* bias = g_beT + e * HDIM + h0 + wn;
#pragma unroll
        for (int mc = 0; mc < 4; ++mc) {
#pragma unroll
            for (int half = 0; half < 2; ++half) {
                const int rrel = wm + mc * 16 + g + half * 8;
                const int m    = m0 + rrel;
                if (m >= cnt) continue;
                const int   tok = g_tok[e][m];
                const float w   = g_gw[e][m];
                float* orow = out + (size_t)tok * HDIM;
#pragma unroll
                for (int nc = 0; nc < 4; ++nc) {
                    const int hn = nc * 8 + t4 * 2;
                    const float v0 = w * (c[mc][nc][half * 2 + 0] + bias[hn]);
                    const float v1 = w * (c[mc][nc][half * 2 + 1] + bias[hn + 1]);
                    asm volatile("red.global.add.v2.f32 [%0], {%1,%2};"
                                 :: "l"(orow + h0 + wn + hn), "f"(v0), "f"(v1) : "memory");
                }
            }
        }
        // Iteration-start sync of the next pop orders all threads' epilogues
        // before the next tile's prologue writes smem.
    }
}

extern "C" void kernel_launch(void* const* d_in, const int* in_sizes, int n_in,
                              void* d_out, int out_size)
{
    const float* x  = (const float*)d_in[0];
    const float* We = (const float*)d_in[1];
    const float* be = (const float*)d_in[2];
    const float* Wg = (const float*)d_in[3];
    const float* bg = (const float*)d_in[4];
    float* out = (float*)d_out;

    cudaFuncSetAttribute(moe_gemm_f16,
                         cudaFuncAttributeMaxDynamicSharedMemorySize, SMEM_BYTES);

    void* cntp = nullptr;
    cudaGetSymbolAddress(&cntp, g_cnt);
    cudaMemsetAsync(cntp, 0, 16 * sizeof(int));

    gate_conv_kernel<<<NTOK / 8 + 512, 256>>>(x, Wg, bg, We, be, out);

    moe_gemm_f16<<<NCTA, 256, SMEM_BYTES>>>(out);
}

// round 16
// speedup vs baseline: 1.0520x; 1.0520x over previous
#include <cuda_runtime.h>
#include <cuda_fp16.h>
#include <cstdint>

// Sparse MoE FFN: T=8192 tokens, H=1024, E=8 experts, top-2 routing.
// fp16 mma m16n8k16 (fp32 accum), BK=32, 4-stage cp.async, ldmatrix with
// register double-buffering and boundary-overlapped fragment loads.
// (R14 configuration — measured optimum — plus epilogue bias hoisting.)

#define NTOK 8192
#define HDIM 1024
#define NEXP 8

#define BM 128
#define BN 128
#define BK 32                   // halves per k-chunk
#define NC (HDIM / BK)          // 32 chunks
#define STAGES 4
#define ROWH 40                 // padded row stride in halves (80 B) -> conflict-free
#define TILEH (BM * ROWH)
#define STAGEH (2 * TILEH)
#define SMEM_BYTES (STAGES * STAGEH * 2)   // 81920 B
#define NCONVB 1024             // We-conversion blocks

// Routing + half scratch.
__device__ int    g_cnt[NEXP];
__device__ int    g_tok[NEXP][NTOK];
__device__ float  g_gw [NEXP][NTOK];
__device__ float  g_beT[NEXP * HDIM];    // bias transposed: [e][h]
__device__ __half g_xh [NTOK * HDIM];
__device__ __half g_weh[NTOK * HDIM];

__device__ __forceinline__ uint32_t pack_h2(float lo, float hi) {
    uint32_t r;
    asm("cvt.rn.f16x2.f32 %0, %1, %2;" : "=r"(r) : "f"(hi), "f"(lo));
    return r;
}

// Fused: blocks [0,1024) gate + convert x + zero out row;
//        blocks [1024,1024+NCONVB) convert We (+ bias transpose in block 1024).
__global__ __launch_bounds__(256) void gate_conv_kernel(
        const float* __restrict__ x,
        const float* __restrict__ Wg,
        const float* __restrict__ bg,
        const float* __restrict__ We,
        const float* __restrict__ be,
        float* __restrict__ out)
{
    if (blockIdx.x >= NTOK / 8) {
        const int bid = blockIdx.x - NTOK / 8;
        if (bid == 0) {
            for (int i = threadIdx.x; i < NEXP * HDIM; i += 256) {
                const int e = i >> 10;
                const int h = i & (HDIM - 1);
                g_beT[i] = be[h * NEXP + e];
            }
        }
        const float4* src = reinterpret_cast<const float4*>(We);
        uint2* dst = reinterpret_cast<uint2*>(g_weh);
        const int n = NTOK * HDIM / 4;
        const int stride = NCONVB * 256;
        for (int i = bid * 256 + threadIdx.x; i < n; i += stride) {
            const float4 v = src[i];
            uint2 o;
            o.x = pack_h2(v.x, v.y);
            o.y = pack_h2(v.z, v.w);
            dst[i] = o;
        }
        return;
    }

    const int warp = threadIdx.x >> 5;
    const int lane = threadIdx.x & 31;
    const int t = blockIdx.x * 8 + warp;

    const float4* x4 = reinterpret_cast<const float4*>(x) + (size_t)t * (HDIM / 4);
    const float4* w4 = reinterpret_cast<const float4*>(Wg);
    uint2* xo = reinterpret_cast<uint2*>(g_xh) + (size_t)t * (HDIM / 4);
    float4* orow = reinterpret_cast<float4*>(out) + (size_t)t * (HDIM / 4);
    const float4 zero4 = make_float4(0.f, 0.f, 0.f, 0.f);

    float acc[NEXP];
#pragma unroll
    for (int e = 0; e < NEXP; ++e) acc[e] = 0.f;

#pragma unroll
    for (int j = 0; j < 8; ++j) {
        const int i4 = lane + j * 32;
        const float4 xv = x4[i4];
        orow[i4] = zero4;                 // zero the output row (replaces memset)
        uint2 o;
        o.x = pack_h2(xv.x, xv.y);
        o.y = pack_h2(xv.z, xv.w);
        xo[i4] = o;
#pragma unroll
        for (int e = 0; e < NEXP; ++e) {
            const float4 wv = w4[e * (HDIM / 4) + i4];
            acc[e] = fmaf(xv.x, wv.x, acc[e]);
            acc[e] = fmaf(xv.y, wv.y, acc[e]);
            acc[e] = fmaf(xv.z, wv.z, acc[e]);
            acc[e] = fmaf(xv.w, wv.w, acc[e]);
        }
    }
#pragma unroll
    for (int e = 0; e < NEXP; ++e) {
#pragma unroll
        for (int off = 16; off > 0; off >>= 1)
            acc[e] += __shfl_xor_sync(0xffffffffu, acc[e], off);
    }

    if (lane == 0) {
        float l[NEXP];
#pragma unroll
        for (int e = 0; e < NEXP; ++e) l[e] = acc[e] + bg[e];
        int e0 = 0;
#pragma unroll
        for (int e = 1; e < NEXP; ++e) if (l[e] > l[e0]) e0 = e;
        int e1 = (e0 == 0) ? 1 : 0;
#pragma unroll
        for (int e = 0; e < NEXP; ++e) {
            if (e == e0) continue;
            if (l[e] > l[e1]) e1 = e;
        }
        const float d = expf(l[e1] - l[e0]);
        const float s = 1.f / (1.f + d);
        int p0 = atomicAdd(&g_cnt[e0], 1);
        g_tok[e0][p0] = t; g_gw[e0][p0] = s;
        int p1 = atomicAdd(&g_cnt[e1], 1);
        g_tok[e1][p1] = t; g_gw[e1][p1] = d * s;
    }
}

__device__ __forceinline__ void cpasync16(void* dst, const void* src) {
    unsigned d = (unsigned)__cvta_generic_to_shared(dst);
    asm volatile("cp.async.cg.shared.global [%0], [%1], 16;" :: "r"(d), "l"(src));
}
__device__ __forceinline__ void ldsm_x4(uint32_t* r, uint32_t addr) {
    asm volatile("ldmatrix.sync.aligned.m8n8.x4.shared.b16 {%0,%1,%2,%3}, [%4];"
                 : "=r"(r[0]), "=r"(r[1]), "=r"(r[2]), "=r"(r[3]) : "r"(addr));
}
__device__ __forceinline__ void mma_f16(float* c, const uint32_t* a, const uint32_t* b) {
    asm volatile(
        "mma.sync.aligned.m16n8k16.row.col.f32.f16.f16.f32 "
        "{%0,%1,%2,%3}, {%4,%5,%6,%7}, {%8,%9}, {%0,%1,%2,%3};"
        : "+f"(c[0]), "+f"(c[1]), "+f"(c[2]), "+f"(c[3])
        : "r"(a[0]), "r"(a[1]), "r"(a[2]), "r"(a[3]), "r"(b[0]), "r"(b[1]));
}

// Grouped GEMM: expert e, tile [m0:m0+128) x [h0:h0+128), K=1024, fp16 inputs.
// 4-stage pipeline, one __syncthreads per chunk, reg-double-buffered frags.
__global__ __launch_bounds__(256, 2) void moe_gemm_f16(
        float* __restrict__ out)
{
    const int e   = blockIdx.z;
    const int cnt = g_cnt[e];
    const int m0  = blockIdx.x * BM;
    if (m0 >= cnt) return;
    const int h0  = blockIdx.y * BN;

    extern __shared__ __half smem[];
    const uint32_t sbase = (uint32_t)__cvta_generic_to_shared(smem);

    const int tid  = threadIdx.x;
    const int wid  = tid >> 5;
    const int lane = tid & 31;
    const int wm   = (wid & 1) * 64;
    const int wn   = (wid >> 1) * 32;
    const int g    = lane >> 2;
    const int t4   = lane & 3;

    // GMEM->SMEM: each thread loads 2 rows x one 16B chunk (8 halves).
    const int lrow = tid >> 2;          // 0..63
    const int lch  = (tid & 3) * 8;     // half offset within row: 0,8,16,24
    const int r0 = min(m0 + lrow,      cnt - 1);
    const int r1 = min(m0 + lrow + 64, cnt - 1);
    const __half* aptr0 = g_xh + (size_t)g_tok[e][r0] * HDIM + lch;
    const __half* aptr1 = g_xh + (size_t)g_tok[e][r1] * HDIM + lch;
    const __half* bptr0 = g_weh + ((size_t)(h0 + lrow)      * NEXP + e) * HDIM + lch;
    const __half* bptr1 = g_weh + ((size_t)(h0 + lrow + 64) * NEXP + e) * HDIM + lch;
    const int sd0 = lrow * ROWH + lch;
    const int sd1 = (lrow + 64) * ROWH + lch;

    // ldmatrix lane-address bases (bytes, within a stage).
    const uint32_t a_lane = (uint32_t)(((wm + (lane & 15)) * ROWH + (lane >> 4) * 8) * 2);
    const uint32_t b_lane = (uint32_t)(((wn + ((lane >> 4) << 3) + (lane & 7)) * ROWH
                                        + ((lane >> 3) & 1) * 8) * 2 + TILEH * 2);

    float c[4][4][4];
#pragma unroll
    for (int i = 0; i < 4; ++i)
#pragma unroll
        for (int j = 0; j < 4; ++j)
#pragma unroll
            for (int q = 0; q < 4; ++q) c[i][j][q] = 0.f;

    uint32_t af[2][4][4], bf[2][2][4];

    // Prologue: commit chunks 0..2 into stages 0..2.
#pragma unroll
    for (int cpre = 0; cpre < STAGES - 1; ++cpre) {
        __half* sA = smem + cpre * STAGEH;
        __half* sB = sA + TILEH;
        const int k = cpre * BK;
        cpasync16(&sA[sd0], aptr0 + k);
        cpasync16(&sA[sd1], aptr1 + k);
        cpasync16(&sB[sd0], bptr0 + k);
        cpasync16(&sB[sd1], bptr1 + k);
        asm volatile("cp.async.commit_group;");
    }
    asm volatile("cp.async.wait_group 2;" ::: "memory");
    __syncthreads();

    // Frags (chunk 0, ks 0) -> buffer 0.
#pragma unroll
    for (int mc = 0; mc < 4; ++mc)
        ldsm_x4(af[0][mc], sbase + a_lane + (uint32_t)(mc * 16 * ROWH * 2));
#pragma unroll
    for (int p = 0; p < 2; ++p)
        ldsm_x4(bf[0][p], sbase + b_lane + (uint32_t)(p * 16 * ROWH * 2));

    for (int ck = 0; ck < NC; ++ck) {
        // Prefetch chunk ck+3 into stage (ck+3)%4 (held chunk ck-1, finished by
        // all warps before the boundary sync entering this iteration).
        if (ck + 3 < NC) {
            const int ns = (ck + 3) % STAGES;
            const int k  = (ck + 3) * BK;
            __half* sA = smem + ns * STAGEH;
            __half* sB = sA + TILEH;
            cpasync16(&sA[sd0], aptr0 + k);
            cpasync16(&sA[sd1], aptr1 + k);
            cpasync16(&sB[sd0], bptr0 + k);
            cpasync16(&sB[sd1], bptr1 + k);
            asm volatile("cp.async.commit_group;");
        }

        const uint32_t stg = sbase + (uint32_t)((ck % STAGES) * STAGEH * 2);
#pragma unroll
        for (int ks = 0; ks < 2; ++ks) {
            const int cur = ks & 1;
            const int nxt = cur ^ 1;
            if (ks == 0) {
                // Prefetch second k-step's fragments of this chunk.
#pragma unroll
                for (int mc = 0; mc < 4; ++mc)
                    ldsm_x4(af[nxt][mc], stg + a_lane + (uint32_t)(mc * 16 * ROWH * 2) + 32u);
#pragma unroll
                for (int p = 0; p < 2; ++p)
                    ldsm_x4(bf[nxt][p], stg + b_lane + (uint32_t)(p * 16 * ROWH * 2) + 32u);
            } else if (ck + 1 < NC) {
                // Boundary: chunk ck+1 resident (<=2 younger groups pending),
                // then load its first k-step; the reg-resident MMA burst below
                // covers the post-barrier LDSM latency.
                if (ck + 3 < NC) {
                    asm volatile("cp.async.wait_group 2;" ::: "memory");
                } else if (ck + 2 < NC) {
                    asm volatile("cp.async.wait_group 1;" ::: "memory");
                } else {
                    asm volatile("cp.async.wait_group 0;" ::: "memory");
                }
                __syncthreads();
                const uint32_t nstg = sbase + (uint32_t)(((ck + 1) % STAGES) * STAGEH * 2);
#pragma unroll
                for (int mc = 0; mc < 4; ++mc)
                    ldsm_x4(af[nxt][mc], nstg + a_lane + (uint32_t)(mc * 16 * ROWH * 2));
#pragma unroll
                for (int p = 0; p < 2; ++p)
                    ldsm_x4(bf[nxt][p], nstg + b_lane + (uint32_t)(p * 16 * ROWH * 2));
            }
#pragma unroll
            for (int mc = 0; mc < 4; ++mc)
#pragma unroll
                for (int nc = 0; nc < 4; ++nc)
                    mma_f16(c[mc][nc], af[cur][mc], &bf[cur][nc >> 1][(nc & 1) * 2]);
        }
    }

    // Epilogue: out[tok,h] += w * (c + beT[e][h]).
    // Hoist the 8 distinct bias values (per thread) into registers once.
    const float* bias = g_beT + e * HDIM + h0 + wn;
    float bias_r[8];
#pragma unroll
    for (int nc = 0; nc < 4; ++nc) {
        bias_r[nc * 2 + 0] = bias[nc * 8 + t4 * 2 + 0];
        bias_r[nc * 2 + 1] = bias[nc * 8 + t4 * 2 + 1];
    }
#pragma unroll
    for (int mc = 0; mc < 4; ++mc) {
#pragma unroll
        for (int half = 0; half < 2; ++half) {
            const int rrel = wm + mc * 16 + g + half * 8;
            const int m    = m0 + rrel;
            if (m >= cnt) continue;
            const int   tok = g_tok[e][m];
            const float w   = g_gw[e][m];
            float* orow = out + (size_t)tok * HDIM;
#pragma unroll
            for (int nc = 0; nc < 4; ++nc) {
                const int hn = nc * 8 + t4 * 2;
                const float v0 = w * (c[mc][nc][half * 2 + 0] + bias_r[nc * 2 + 0]);
                const float v1 = w * (c[mc][nc][half * 2 + 1] + bias_r[nc * 2 + 1]);
                asm volatile("red.global.add.v2.f32 [%0], {%1,%2};"
                             :: "l"(orow + h0 + wn + hn), "f"(v0), "f"(v1) : "memory");
            }
        }
    }
}

extern "C" void kernel_launch(void* const* d_in, const int* in_sizes, int n_in,
                              void* d_out, int out_size)
{
    const float* x  = (const float*)d_in[0];
    const float* We = (const float*)d_in[1];
    const float* be = (const float*)d_in[2];
    const float* Wg = (const float*)d_in[3];
    const float* bg = (const float*)d_in[4];
    float* out = (float*)d_out;

    cudaFuncSetAttribute(moe_gemm_f16,
                         cudaFuncAttributeMaxDynamicSharedMemorySize, SMEM_BYTES);

    void* cntp = nullptr;
    cudaGetSymbolAddress(&cntp, g_cnt);
    cudaMemsetAsync(cntp, 0, NEXP * sizeof(int));

    gate_conv_kernel<<<NTOK / 8 + NCONVB, 256>>>(x, Wg, bg, We, be, out);

    dim3 grid(NTOK / BM, HDIM / BN, NEXP);
    moe_gemm_f16<<<grid, 256, SMEM_BYTES>>>(out);
}